// round 15
// baseline (speedup 1.0000x reference)
#include <cuda_runtime.h>
#include <cuda_bf16.h>
#include <cstdint>
#include <math.h>

#define NB 2048
#define NC 100
#define NK 8
#define ND 64
#define NCK 800
#define NPAIR 2080
#define PDIM 2145
#define PPAD 2176
#define KE2  (2 * PPAD)        // 4352: seg0 = hi, seg1 = lo
#define CK2  832
#define BM 64
#define BN 64
#define KSTG 32
#define NST2 (PPAD / KSTG)     // 68 stages
#define STAGE_B 20480u         // 4 tiles * 64 rows * 80 B
#define TILE_B  5120u
#define SMEM_B  (3 * 20480)    // 61440

__device__ __align__(128) __nv_bfloat16 g_G2[(size_t)NB * KE2];   // [b][k]: gh | gl
__device__ __align__(128) __nv_bfloat16 g_A2[(size_t)CK2 * KE2];  // [ck][k]: ah | al
__device__ __align__(128) float g_cls[NB * NC];

// ---------------- helpers ----------------
__device__ __forceinline__ uint32_t smem_u32(const void* p) {
    uint32_t a;
    asm("{ .reg .u64 t; cvta.to.shared.u64 t, %1; cvt.u32.u64 %0, t; }" : "=r"(a) : "l"(p));
    return a;
}
__device__ __forceinline__ void cp16(uint32_t saddr, const void* g) {
    asm volatile("cp.async.cg.shared.global [%0], [%1], 16;\n" :: "r"(saddr), "l"(g));
}
#define CP_COMMIT()  asm volatile("cp.async.commit_group;\n" ::: "memory")
#define CP_WAIT(n)   asm volatile("cp.async.wait_group %0;\n" :: "n"(n) : "memory")

__device__ __forceinline__ void ldsm4(uint32_t* r, uint32_t addr) {
    asm volatile("ldmatrix.sync.aligned.m8n8.x4.shared.b16 {%0,%1,%2,%3}, [%4];"
                 : "=r"(r[0]), "=r"(r[1]), "=r"(r[2]), "=r"(r[3]) : "r"(addr));
}
__device__ __forceinline__ void mma16816(float* d, const uint32_t* a, uint32_t b0, uint32_t b1) {
    asm volatile("mma.sync.aligned.m16n8k16.row.col.f32.bf16.bf16.f32 "
                 "{%0,%1,%2,%3}, {%4,%5,%6,%7}, {%8,%9}, {%0,%1,%2,%3};"
                 : "+f"(d[0]), "+f"(d[1]), "+f"(d[2]), "+f"(d[3])
                 : "r"(a[0]), "r"(a[1]), "r"(a[2]), "r"(a[3]), "r"(b0), "r"(b1));
}

// dummy launch: keeps the GEMM in ncu's profiled (4th) slot
__global__ void dummy_kernel() {}

// ---------------- Kernel 1: prep (syncless column-solve L^{-1}, packed A) --
__device__ __forceinline__ void storeA(int ck, int p, float v) {
    __nv_bfloat16 h = __float2bfloat16(v);
    __nv_bfloat16 l = __float2bfloat16(v - __bfloat162float(h));
    const size_t base = (size_t)ck * KE2;
    g_A2[base + p] = h;
    g_A2[base + PPAD + p] = l;
}

__global__ void prep_kernel(const float* __restrict__ mix,
                            const float* __restrict__ loc,
                            const float* __restrict__ tril) {
    const int ck = blockIdx.x, tid = threadIdx.x;
    if (ck >= NCK) {
        const size_t base = (size_t)ck * KE2;
        for (int p = tid; p < KE2; p += 64) g_A2[base + p] = __float2bfloat16(0.0f);
        return;
    }
    const int c = ck >> 3, k = ck & 7;
    __shared__ float Lsh[ND][65];
    __shared__ float Msh[ND][65];
    __shared__ float locsh[ND], vsh[ND], red[ND];
    __shared__ int rs[ND + 1];

    const float* Lg = tril + (size_t)ck * ND * ND;
    for (int idx = tid; idx < ND * ND; idx += 64) Lsh[idx >> 6][idx & 63] = Lg[idx];
    locsh[tid] = loc[ck * ND + tid];
    rs[tid] = tid * ND - tid * (tid - 1) / 2;
    if (tid == 0) rs[ND] = NPAIR;
    __syncthreads();
    const float mydiag = Lsh[tid][tid];

    // Column-parallel inverse: thread `col` owns column `col` of M = L^{-1}.
    // M[i][col] depends only on M[t][col] (same column, same thread) and the
    // stable Lsh -> NO __syncthreads inside the solve; 64 independent solves.
    {
        const int col = tid;
        #pragma unroll 1
        for (int i = col; i < ND; ++i) {
            float s = (i == col) ? 1.0f : 0.0f;
            #pragma unroll 1
            for (int t = col; t < i; ++t) s -= Lsh[i][t] * Msh[t][col];
            Msh[i][col] = s / Lsh[i][i];
        }
    }
    __syncthreads();

    float vd = 0.0f;                        // v = M*mu
    for (int t = 0; t <= tid; ++t) vd += Msh[tid][t] * locsh[t];
    vsh[tid] = vd;
    __syncthreads();
    float wd = 0.0f;                        // w = A*mu
    for (int t = tid; t < ND; ++t) wd += Msh[t][tid] * vsh[t];
    storeA(ck, NPAIR + tid, -2.0f * wd);

    red[tid] = vd * vd;  __syncthreads();
    for (int o = 32; o > 0; o >>= 1) { if (tid < o) red[tid] += red[tid + o]; __syncthreads(); }
    const float cst = red[0];  __syncthreads();
    red[tid] = logf(fabsf(mydiag));  __syncthreads();
    for (int o = 32; o > 0; o >>= 1) { if (tid < o) red[tid] += red[tid + o]; __syncthreads(); }
    const float logdet = red[0];

    float ml[NK], mmx = -1e30f;
    #pragma unroll
    for (int kk = 0; kk < NK; ++kk) { ml[kk] = mix[c * NK + kk]; mmx = fmaxf(mmx, ml[kk]); }
    float msum = 0.0f;
    #pragma unroll
    for (int kk = 0; kk < NK; ++kk) msum += expf(ml[kk] - mmx);
    const float mixlog = ml[k] - (mmx + logf(msum));
    const float bias = -0.5f * cst - 32.0f * 1.8378770664093454836f - logdet + mixlog;
    if (tid == 0) storeA(ck, 2144, -2.0f * bias);
    for (int p = PDIM + tid; p < PPAD; p += 64) storeA(ck, p, 0.0f);

    int i = 0;                              // packed A = M^T M
    for (int p = tid; p < NPAIR; p += 64) {
        while (rs[i + 1] <= p) ++i;
        const int j = i + (p - rs[i]);
        float s = 0.0f;
        for (int t = j; t < ND; ++t) s += Msh[t][i] * Msh[t][j];
        storeA(ck, p, (i == j) ? s : 2.0f * s);
    }
}

// ---------------- Kernel 2: G rows (bf16 hi/lo, [b][k] layout) -------------
__global__ void gbuild_kernel(const float* __restrict__ rep) {
    __shared__ float xs[64 * 65];
    __shared__ int is[64], js[64];
    const int p0 = blockIdx.x * 64, b0 = blockIdx.y * 64;
    const int tid = threadIdx.x, lane = tid & 31, w = tid >> 5;

    for (int f = tid; f < 64 * 64; f += 256) {
        const int bl = f >> 6, d = f & 63;
        xs[bl * 65 + d] = rep[(size_t)(b0 + bl) * ND + d];
    }
    if (tid < 64) {
        const int p = p0 + tid;
        if (p < NPAIR) {
            int i = 0;
            while ((i + 1) * ND - (i + 1) * i / 2 <= p) ++i;
            const int rsI = i * ND - i * (i - 1) / 2;
            is[tid] = i; js[tid] = i + (p - rsI);
        } else if (p < 2144) { is[tid] = -1; js[tid] = p - NPAIR; }
        else if (p == 2144) { is[tid] = -2; js[tid] = 0; }
        else { is[tid] = -3; js[tid] = 0; }
    }
    __syncthreads();

    const int pl = 2 * lane;
    const int i0 = is[pl], j0 = js[pl], i1 = is[pl + 1], j1 = js[pl + 1];
    #pragma unroll 2
    for (int it = 0; it < 8; ++it) {
        const int bl = w + 8 * it;
        const float* xr = &xs[bl * 65];
        float v0 = (i0 >= 0) ? xr[i0] * xr[j0] : (i0 == -1 ? xr[j0] : (i0 == -2 ? 1.0f : 0.0f));
        float v1 = (i1 >= 0) ? xr[i1] * xr[j1] : (i1 == -1 ? xr[j1] : (i1 == -2 ? 1.0f : 0.0f));
        __nv_bfloat16 h0 = __float2bfloat16(v0), h1 = __float2bfloat16(v1);
        __nv_bfloat16 l0 = __float2bfloat16(v0 - __bfloat162float(h0));
        __nv_bfloat16 l1 = __float2bfloat16(v1 - __bfloat162float(h1));
        const size_t base = (size_t)(b0 + bl) * KE2 + p0 + pl;
        *(__nv_bfloat162*)(g_G2 + base)        = __nv_bfloat162(h0, h1);  // gh
        *(__nv_bfloat162*)(g_G2 + base + PPAD) = __nv_bfloat162(l0, l1);  // gl
    }
}

// ---------------- Kernel 3: split-K-in-register GEMM + fused lse -----------
// (verbatim R12 winner: 84.7us, tensor 42.9%)
__global__ void __launch_bounds__(128, 3) gemm_kernel() {
    extern __shared__ __align__(16) char smem_dyn[];
    const uint32_t sm0 = smem_u32(smem_dyn);
    const int tid = threadIdx.x, lane = tid & 31, wid = tid >> 5;
    const int wm = wid & 1, wn = wid >> 1;
    const int bm0 = blockIdx.x * BM, bn0 = blockIdx.y * BN;
    const __nv_bfloat16* gA = g_G2 + (size_t)bm0 * KE2;
    const __nv_bfloat16* gB = g_A2 + (size_t)bn0 * KE2;

    float acc[2][4][4];
    #pragma unroll
    for (int mt = 0; mt < 2; ++mt)
        #pragma unroll
        for (int nt = 0; nt < 4; ++nt)
            #pragma unroll
            for (int e = 0; e < 4; ++e) acc[mt][nt][e] = 0.0f;

    const int aRow = wm * 32 + (lane & 7) + ((lane >> 3) & 1) * 8;   // + mt*16
    const int aColB = ((lane >> 4) * 8) * 2;                         // + h*32
    const int bRow = wn * 32 + (lane & 7) + ((lane >> 4) & 1) * 8;   // + nt2*16
    const int bColB = (((lane >> 3) & 1) * 8) * 2;                   // + h*32

    // tiles: 0=Agh 1=Agl 2=Bah 3=Bal ; 8 cp16 per thread per stage
    #define LOAD_STAGE(s, buf) do {                                          \
        const int k0_ = (s) * KSTG;                                          \
        _Pragma("unroll")                                                    \
        for (int q = 0; q < 8; ++q) {                                        \
            const int f = tid + 128 * q;                                     \
            const int tile = f >> 8, ft = f & 255;                           \
            const int r = ft >> 2, cc = ft & 3;                              \
            const __nv_bfloat16* gp = (tile < 2) ? gA : gB;                  \
            const int seg = (tile & 1) * PPAD;                               \
            cp16(sm0 + (buf) * STAGE_B + tile * TILE_B + r * 80 + cc * 16,   \
                 gp + (size_t)r * KE2 + seg + k0_ + cc * 8);                 \
        }                                                                    \
        CP_COMMIT();                                                         \
    } while (0)

    LOAD_STAGE(0, 0);
    LOAD_STAGE(1, 1);

    #pragma unroll 1
    for (int s = 0; s < NST2; ++s) {
        const int buf = s % 3;
        if (s + 1 < NST2) CP_WAIT(1);      // stage s resident, s+1 may pend
        else              CP_WAIT(0);
        __syncthreads();                   // publish stage s; retire (s+2)%3
        if (s + 2 < NST2) LOAD_STAGE(s + 2, (s + 2) % 3);

        const uint32_t stB = sm0 + buf * STAGE_B;
        #pragma unroll
        for (int h = 0; h < 2; ++h) {
            uint32_t agh[2][4], agl[2][4], bah[2][4], bal[2][4];
            #pragma unroll
            for (int mt = 0; mt < 2; ++mt) {
                const uint32_t ra = (uint32_t)((aRow + mt * 16) * 80 + aColB + h * 32);
                ldsm4(agh[mt], stB + ra);
                ldsm4(agl[mt], stB + TILE_B + ra);
            }
            #pragma unroll
            for (int nt2 = 0; nt2 < 2; ++nt2) {
                const uint32_t rb = (uint32_t)((bRow + nt2 * 16) * 80 + bColB + h * 32);
                ldsm4(bah[nt2], stB + 2 * TILE_B + rb);
                ldsm4(bal[nt2], stB + 3 * TILE_B + rb);
            }
            #pragma unroll
            for (int mt = 0; mt < 2; ++mt)
                #pragma unroll
                for (int nt = 0; nt < 4; ++nt) {
                    const uint32_t bh0 = bah[nt >> 1][(nt & 1) * 2];
                    const uint32_t bh1 = bah[nt >> 1][(nt & 1) * 2 + 1];
                    const uint32_t bl0 = bal[nt >> 1][(nt & 1) * 2];
                    const uint32_t bl1 = bal[nt >> 1][(nt & 1) * 2 + 1];
                    mma16816(acc[mt][nt], agh[mt], bh0, bh1);
                    mma16816(acc[mt][nt], agl[mt], bh0, bh1);
                    mma16816(acc[mt][nt], agh[mt], bl0, bl1);
                }
        }
    }

    // Epilogue: each n8 tile = one class (8 mixture comps). lse across the
    // 4-lane quad (each thread holds 2 cols), rows gID and gID+8.
    const int gID = lane >> 2, tig = lane & 3;
    #pragma unroll
    for (int mt = 0; mt < 2; ++mt) {
        const int row0 = bm0 + wm * 32 + mt * 16 + gID;
        #pragma unroll
        for (int nt = 0; nt < 4; ++nt) {
            const int c = bn0 / 8 + wn * 4 + nt;
            #pragma unroll
            for (int half = 0; half < 2; ++half) {
                const float v0 = -0.5f * acc[mt][nt][2 * half];
                const float v1 = -0.5f * acc[mt][nt][2 * half + 1];
                float m = fmaxf(v0, v1);
                float se = expf(v0 - m) + expf(v1 - m);
                #pragma unroll
                for (int o = 1; o <= 2; o <<= 1) {
                    const float pm = __shfl_xor_sync(0xffffffffu, m, o);
                    const float ps = __shfl_xor_sync(0xffffffffu, se, o);
                    const float M2 = fmaxf(m, pm);
                    se = se * expf(m - M2) + ps * expf(pm - M2);
                    m = M2;
                }
                if (tig == 0 && c < NC)
                    g_cls[(size_t)(row0 + 8 * half) * NC + c] = m + logf(se);
            }
        }
    }
}

// ---------------- Kernel 4: row log_softmax over C=100 ---------------------
__global__ void softmax_kernel(float* __restrict__ out) {
    const int lane = threadIdx.x & 31;
    const int b = blockIdx.x * 8 + (threadIdx.x >> 5);
    float v[4];
    float mx = -INFINITY;
    #pragma unroll
    for (int q = 0; q < 4; ++q) {
        const int cc = lane + 32 * q;
        v[q] = (cc < NC) ? g_cls[b * NC + cc] : -INFINITY;
        mx = fmaxf(mx, v[q]);
    }
    #pragma unroll
    for (int o = 16; o > 0; o >>= 1) mx = fmaxf(mx, __shfl_xor_sync(0xffffffffu, mx, o));
    float sum = 0.0f;
    #pragma unroll
    for (int q = 0; q < 4; ++q) {
        const int cc = lane + 32 * q;
        if (cc < NC) sum += expf(v[q] - mx);
    }
    #pragma unroll
    for (int o = 16; o > 0; o >>= 1) sum += __shfl_xor_sync(0xffffffffu, sum, o);
    const float lse = mx + logf(sum);
    #pragma unroll
    for (int q = 0; q < 4; ++q) {
        const int cc = lane + 32 * q;
        if (cc < NC) out[b * NC + cc] = v[q] - lse;
    }
}

extern "C" void kernel_launch(void* const* d_in, const int* in_sizes, int n_in,
                              void* d_out, int out_size) {
    const float *rep = nullptr, *mix = nullptr, *loc = nullptr, *tril = nullptr;
    for (int i = 0; i < n_in; ++i) {
        switch (in_sizes[i]) {
            case NB * ND:       rep  = (const float*)d_in[i]; break;
            case NC * NK:       mix  = (const float*)d_in[i]; break;
            case NCK * ND:      loc  = (const float*)d_in[i]; break;
            case NCK * ND * ND: tril = (const float*)d_in[i]; break;
            default: break;
        }
    }
    if (!rep || !mix || !loc || !tril) {
        rep  = (const float*)d_in[0];
        mix  = (const float*)d_in[1];
        loc  = (const float*)d_in[2];
        tril = (const float*)d_in[3];
    }
    cudaFuncSetAttribute(gemm_kernel, cudaFuncAttributeMaxDynamicSharedMemorySize, SMEM_B);
    cudaFuncSetAttribute(gemm_kernel, cudaFuncAttributePreferredSharedMemoryCarveout, 100);
    dummy_kernel<<<1, 32>>>();                       // GEMM stays in ncu's 4th slot
    prep_kernel<<<CK2, 64>>>(mix, loc, tril);
    gbuild_kernel<<<dim3(PPAD / 64, NB / 64), 256>>>(rep);
    gemm_kernel<<<dim3(NB / BM, CK2 / BN), 128, SMEM_B>>>();
    softmax_kernel<<<NB / 8, 256>>>((float*)d_out);
}

// round 16
// speedup vs baseline: 1.2943x; 1.2943x over previous
#include <cuda_runtime.h>
#include <cuda_bf16.h>
#include <cstdint>
#include <math.h>

#define NB 2048
#define NC 100
#define NK 8
#define ND 64
#define NCK 800
#define NPAIR 2080
#define PDIM 2145
#define PPAD 2176
#define KE2  (2 * PPAD)        // 4352: seg0 = hi, seg1 = lo
#define CK2  832
#define BM 64
#define BN 64
#define KSTG 32
#define NST2 (PPAD / KSTG)     // 68 stages
#define STAGE_B 20480u         // 4 tiles * 64 rows * 80 B
#define TILE_B  5120u
#define SMEM_B  (3 * 20480)    // 61440

__device__ __align__(128) __nv_bfloat16 g_G2[(size_t)NB * KE2];   // [b][k]: gh | gl
__device__ __align__(128) __nv_bfloat16 g_A2[(size_t)CK2 * KE2];  // [ck][k]: ah | al
__device__ __align__(128) float g_cls[NB * NC];

// ---------------- helpers ----------------
__device__ __forceinline__ uint32_t smem_u32(const void* p) {
    uint32_t a;
    asm("{ .reg .u64 t; cvta.to.shared.u64 t, %1; cvt.u32.u64 %0, t; }" : "=r"(a) : "l"(p));
    return a;
}
__device__ __forceinline__ void cp16(uint32_t saddr, const void* g) {
    asm volatile("cp.async.cg.shared.global [%0], [%1], 16;\n" :: "r"(saddr), "l"(g));
}
#define CP_COMMIT()  asm volatile("cp.async.commit_group;\n" ::: "memory")
#define CP_WAIT(n)   asm volatile("cp.async.wait_group %0;\n" :: "n"(n) : "memory")

__device__ __forceinline__ void ldsm4(uint32_t* r, uint32_t addr) {
    asm volatile("ldmatrix.sync.aligned.m8n8.x4.shared.b16 {%0,%1,%2,%3}, [%4];"
                 : "=r"(r[0]), "=r"(r[1]), "=r"(r[2]), "=r"(r[3]) : "r"(addr));
}
__device__ __forceinline__ void mma16816(float* d, const uint32_t* a, uint32_t b0, uint32_t b1) {
    asm volatile("mma.sync.aligned.m16n8k16.row.col.f32.bf16.bf16.f32 "
                 "{%0,%1,%2,%3}, {%4,%5,%6,%7}, {%8,%9}, {%0,%1,%2,%3};"
                 : "+f"(d[0]), "+f"(d[1]), "+f"(d[2]), "+f"(d[3])
                 : "r"(a[0]), "r"(a[1]), "r"(a[2]), "r"(a[3]), "r"(b0), "r"(b1));
}

// dummy launch: slot padding (ncu profiles the 4th launch)
__global__ void dummy_kernel() {}

// ---------------- Kernel 1: prep (right-looking register solve, packed A) --
__device__ __forceinline__ void storeA(int ck, int p, float v) {
    __nv_bfloat16 h = __float2bfloat16(v);
    __nv_bfloat16 l = __float2bfloat16(v - __bfloat162float(h));
    const size_t base = (size_t)ck * KE2;
    g_A2[base + p] = h;
    g_A2[base + PPAD + p] = l;
}

__global__ void __launch_bounds__(64) prep_kernel(const float* __restrict__ mix,
                                                  const float* __restrict__ loc,
                                                  const float* __restrict__ tril) {
    const int ck = blockIdx.x, tid = threadIdx.x;
    if (ck >= NCK) {
        const size_t base = (size_t)ck * KE2;
        for (int p = tid; p < KE2; p += 64) g_A2[base + p] = __float2bfloat16(0.0f);
        return;
    }
    const int c = ck >> 3, k = ck & 7;
    __shared__ float Lsh[ND][65];
    __shared__ float Msh[ND][65];
    __shared__ float locsh[ND], vsh[ND], red[ND], rdiag[ND];
    __shared__ int rs[ND + 1];

    const float* Lg = tril + (size_t)ck * ND * ND;
    for (int idx = tid; idx < ND * ND; idx += 64) Lsh[idx >> 6][idx & 63] = Lg[idx];
    locsh[tid] = loc[ck * ND + tid];
    rs[tid] = tid * ND - tid * (tid - 1) / 2;
    if (tid == 0) rs[ND] = NPAIR;
    __syncthreads();
    const float mydiag = Lsh[tid][tid];
    rdiag[tid] = 1.0f / mydiag;
    __syncthreads();

    // Right-looking register solve: thread c owns column c of M = L^{-1}.
    // P[j] accumulates sum_{t<j} L[j][t]*M[t][c]; updates are INDEPENDENT
    // FMAs (pipelined), critical path is just 64 x (FMA+MUL). No barriers.
    // For i < c everything is zero (uniform, no divergence).
    {
        float P[ND];
        #pragma unroll
        for (int i = 0; i < ND; ++i) P[i] = 0.0f;
        #pragma unroll
        for (int i = 0; i < ND; ++i) {
            const float m = (((i == tid) ? 1.0f : 0.0f) - P[i]) * rdiag[i];
            Msh[i][tid] = m;
            #pragma unroll
            for (int j = i + 1; j < ND; ++j)
                P[j] = fmaf(Lsh[j][i], m, P[j]);
        }
    }
    __syncthreads();

    float vd = 0.0f;                        // v = M*mu
    for (int t = 0; t <= tid; ++t) vd += Msh[tid][t] * locsh[t];
    vsh[tid] = vd;
    __syncthreads();
    float wd = 0.0f;                        // w = A*mu
    for (int t = tid; t < ND; ++t) wd += Msh[t][tid] * vsh[t];
    storeA(ck, NPAIR + tid, -2.0f * wd);

    red[tid] = vd * vd;  __syncthreads();
    for (int o = 32; o > 0; o >>= 1) { if (tid < o) red[tid] += red[tid + o]; __syncthreads(); }
    const float cst = red[0];  __syncthreads();
    red[tid] = logf(fabsf(mydiag));  __syncthreads();
    for (int o = 32; o > 0; o >>= 1) { if (tid < o) red[tid] += red[tid + o]; __syncthreads(); }
    const float logdet = red[0];

    float ml[NK], mmx = -1e30f;
    #pragma unroll
    for (int kk = 0; kk < NK; ++kk) { ml[kk] = mix[c * NK + kk]; mmx = fmaxf(mmx, ml[kk]); }
    float msum = 0.0f;
    #pragma unroll
    for (int kk = 0; kk < NK; ++kk) msum += expf(ml[kk] - mmx);
    const float mixlog = ml[k] - (mmx + logf(msum));
    const float bias = -0.5f * cst - 32.0f * 1.8378770664093454836f - logdet + mixlog;
    if (tid == 0) storeA(ck, 2144, -2.0f * bias);
    for (int p = PDIM + tid; p < PPAD; p += 64) storeA(ck, p, 0.0f);

    int i = 0;                              // packed A = M^T M
    for (int p = tid; p < NPAIR; p += 64) {
        while (rs[i + 1] <= p) ++i;
        const int j = i + (p - rs[i]);
        float s = 0.0f;
        for (int t = j; t < ND; ++t) s += Msh[t][i] * Msh[t][j];
        storeA(ck, p, (i == j) ? s : 2.0f * s);
    }
}

// ---------------- Kernel 2: G rows (bf16 hi/lo, [b][k] layout) -------------
__global__ void gbuild_kernel(const float* __restrict__ rep) {
    __shared__ float xs[64 * 65];
    __shared__ int is[64], js[64];
    const int p0 = blockIdx.x * 64, b0 = blockIdx.y * 64;
    const int tid = threadIdx.x, lane = tid & 31, w = tid >> 5;

    for (int f = tid; f < 64 * 64; f += 256) {
        const int bl = f >> 6, d = f & 63;
        xs[bl * 65 + d] = rep[(size_t)(b0 + bl) * ND + d];
    }
    if (tid < 64) {
        const int p = p0 + tid;
        if (p < NPAIR) {
            int i = 0;
            while ((i + 1) * ND - (i + 1) * i / 2 <= p) ++i;
            const int rsI = i * ND - i * (i - 1) / 2;
            is[tid] = i; js[tid] = i + (p - rsI);
        } else if (p < 2144) { is[tid] = -1; js[tid] = p - NPAIR; }
        else if (p == 2144) { is[tid] = -2; js[tid] = 0; }
        else { is[tid] = -3; js[tid] = 0; }
    }
    __syncthreads();

    const int pl = 2 * lane;
    const int i0 = is[pl], j0 = js[pl], i1 = is[pl + 1], j1 = js[pl + 1];
    #pragma unroll 2
    for (int it = 0; it < 8; ++it) {
        const int bl = w + 8 * it;
        const float* xr = &xs[bl * 65];
        float v0 = (i0 >= 0) ? xr[i0] * xr[j0] : (i0 == -1 ? xr[j0] : (i0 == -2 ? 1.0f : 0.0f));
        float v1 = (i1 >= 0) ? xr[i1] * xr[j1] : (i1 == -1 ? xr[j1] : (i1 == -2 ? 1.0f : 0.0f));
        __nv_bfloat16 h0 = __float2bfloat16(v0), h1 = __float2bfloat16(v1);
        __nv_bfloat16 l0 = __float2bfloat16(v0 - __bfloat162float(h0));
        __nv_bfloat16 l1 = __float2bfloat16(v1 - __bfloat162float(h1));
        const size_t base = (size_t)(b0 + bl) * KE2 + p0 + pl;
        *(__nv_bfloat162*)(g_G2 + base)        = __nv_bfloat162(h0, h1);  // gh
        *(__nv_bfloat162*)(g_G2 + base + PPAD) = __nv_bfloat162(l0, l1);  // gl
    }
}

// ---------------- Kernel 3: split-K-in-register GEMM + fused lse -----------
// (verbatim R12 winner: 84.7us, tensor 42.9%)
__global__ void __launch_bounds__(128, 3) gemm_kernel() {
    extern __shared__ __align__(16) char smem_dyn[];
    const uint32_t sm0 = smem_u32(smem_dyn);
    const int tid = threadIdx.x, lane = tid & 31, wid = tid >> 5;
    const int wm = wid & 1, wn = wid >> 1;
    const int bm0 = blockIdx.x * BM, bn0 = blockIdx.y * BN;
    const __nv_bfloat16* gA = g_G2 + (size_t)bm0 * KE2;
    const __nv_bfloat16* gB = g_A2 + (size_t)bn0 * KE2;

    float acc[2][4][4];
    #pragma unroll
    for (int mt = 0; mt < 2; ++mt)
        #pragma unroll
        for (int nt = 0; nt < 4; ++nt)
            #pragma unroll
            for (int e = 0; e < 4; ++e) acc[mt][nt][e] = 0.0f;

    const int aRow = wm * 32 + (lane & 7) + ((lane >> 3) & 1) * 8;   // + mt*16
    const int aColB = ((lane >> 4) * 8) * 2;                         // + h*32
    const int bRow = wn * 32 + (lane & 7) + ((lane >> 4) & 1) * 8;   // + nt2*16
    const int bColB = (((lane >> 3) & 1) * 8) * 2;                   // + h*32

    // tiles: 0=Agh 1=Agl 2=Bah 3=Bal ; 8 cp16 per thread per stage
    #define LOAD_STAGE(s, buf) do {                                          \
        const int k0_ = (s) * KSTG;                                          \
        _Pragma("unroll")                                                    \
        for (int q = 0; q < 8; ++q) {                                        \
            const int f = tid + 128 * q;                                     \
            const int tile = f >> 8, ft = f & 255;                           \
            const int r = ft >> 2, cc = ft & 3;                              \
            const __nv_bfloat16* gp = (tile < 2) ? gA : gB;                  \
            const int seg = (tile & 1) * PPAD;                               \
            cp16(sm0 + (buf) * STAGE_B + tile * TILE_B + r * 80 + cc * 16,   \
                 gp + (size_t)r * KE2 + seg + k0_ + cc * 8);                 \
        }                                                                    \
        CP_COMMIT();                                                         \
    } while (0)

    LOAD_STAGE(0, 0);
    LOAD_STAGE(1, 1);

    #pragma unroll 1
    for (int s = 0; s < NST2; ++s) {
        const int buf = s % 3;
        if (s + 1 < NST2) CP_WAIT(1);      // stage s resident, s+1 may pend
        else              CP_WAIT(0);
        __syncthreads();                   // publish stage s; retire (s+2)%3
        if (s + 2 < NST2) LOAD_STAGE(s + 2, (s + 2) % 3);

        const uint32_t stB = sm0 + buf * STAGE_B;
        #pragma unroll
        for (int h = 0; h < 2; ++h) {
            uint32_t agh[2][4], agl[2][4], bah[2][4], bal[2][4];
            #pragma unroll
            for (int mt = 0; mt < 2; ++mt) {
                const uint32_t ra = (uint32_t)((aRow + mt * 16) * 80 + aColB + h * 32);
                ldsm4(agh[mt], stB + ra);
                ldsm4(agl[mt], stB + TILE_B + ra);
            }
            #pragma unroll
            for (int nt2 = 0; nt2 < 2; ++nt2) {
                const uint32_t rb = (uint32_t)((bRow + nt2 * 16) * 80 + bColB + h * 32);
                ldsm4(bah[nt2], stB + 2 * TILE_B + rb);
                ldsm4(bal[nt2], stB + 3 * TILE_B + rb);
            }
            #pragma unroll
            for (int mt = 0; mt < 2; ++mt)
                #pragma unroll
                for (int nt = 0; nt < 4; ++nt) {
                    const uint32_t bh0 = bah[nt >> 1][(nt & 1) * 2];
                    const uint32_t bh1 = bah[nt >> 1][(nt & 1) * 2 + 1];
                    const uint32_t bl0 = bal[nt >> 1][(nt & 1) * 2];
                    const uint32_t bl1 = bal[nt >> 1][(nt & 1) * 2 + 1];
                    mma16816(acc[mt][nt], agh[mt], bh0, bh1);
                    mma16816(acc[mt][nt], agl[mt], bh0, bh1);
                    mma16816(acc[mt][nt], agh[mt], bl0, bl1);
                }
        }
    }

    // Epilogue: each n8 tile = one class (8 mixture comps). lse across the
    // 4-lane quad (each thread holds 2 cols), rows gID and gID+8.
    const int gID = lane >> 2, tig = lane & 3;
    #pragma unroll
    for (int mt = 0; mt < 2; ++mt) {
        const int row0 = bm0 + wm * 32 + mt * 16 + gID;
        #pragma unroll
        for (int nt = 0; nt < 4; ++nt) {
            const int c = bn0 / 8 + wn * 4 + nt;
            #pragma unroll
            for (int half = 0; half < 2; ++half) {
                const float v0 = -0.5f * acc[mt][nt][2 * half];
                const float v1 = -0.5f * acc[mt][nt][2 * half + 1];
                float m = fmaxf(v0, v1);
                float se = expf(v0 - m) + expf(v1 - m);
                #pragma unroll
                for (int o = 1; o <= 2; o <<= 1) {
                    const float pm = __shfl_xor_sync(0xffffffffu, m, o);
                    const float ps = __shfl_xor_sync(0xffffffffu, se, o);
                    const float M2 = fmaxf(m, pm);
                    se = se * expf(m - M2) + ps * expf(pm - M2);
                    m = M2;
                }
                if (tig == 0 && c < NC)
                    g_cls[(size_t)(row0 + 8 * half) * NC + c] = m + logf(se);
            }
        }
    }
}

// ---------------- Kernel 4: row log_softmax over C=100 ---------------------
__global__ void softmax_kernel(float* __restrict__ out) {
    const int lane = threadIdx.x & 31;
    const int b = blockIdx.x * 8 + (threadIdx.x >> 5);
    float v[4];
    float mx = -INFINITY;
    #pragma unroll
    for (int q = 0; q < 4; ++q) {
        const int cc = lane + 32 * q;
        v[q] = (cc < NC) ? g_cls[b * NC + cc] : -INFINITY;
        mx = fmaxf(mx, v[q]);
    }
    #pragma unroll
    for (int o = 16; o > 0; o >>= 1) mx = fmaxf(mx, __shfl_xor_sync(0xffffffffu, mx, o));
    float sum = 0.0f;
    #pragma unroll
    for (int q = 0; q < 4; ++q) {
        const int cc = lane + 32 * q;
        if (cc < NC) sum += expf(v[q] - mx);
    }
    #pragma unroll
    for (int o = 16; o > 0; o >>= 1) sum += __shfl_xor_sync(0xffffffffu, sum, o);
    const float lse = mx + logf(sum);
    #pragma unroll
    for (int q = 0; q < 4; ++q) {
        const int cc = lane + 32 * q;
        if (cc < NC) out[b * NC + cc] = v[q] - lse;
    }
}

extern "C" void kernel_launch(void* const* d_in, const int* in_sizes, int n_in,
                              void* d_out, int out_size) {
    const float *rep = nullptr, *mix = nullptr, *loc = nullptr, *tril = nullptr;
    for (int i = 0; i < n_in; ++i) {
        switch (in_sizes[i]) {
            case NB * ND:       rep  = (const float*)d_in[i]; break;
            case NC * NK:       mix  = (const float*)d_in[i]; break;
            case NCK * ND:      loc  = (const float*)d_in[i]; break;
            case NCK * ND * ND: tril = (const float*)d_in[i]; break;
            default: break;
        }
    }
    if (!rep || !mix || !loc || !tril) {
        rep  = (const float*)d_in[0];
        mix  = (const float*)d_in[1];
        loc  = (const float*)d_in[2];
        tril = (const float*)d_in[3];
    }
    cudaFuncSetAttribute(gemm_kernel, cudaFuncAttributeMaxDynamicSharedMemorySize, SMEM_B);
    cudaFuncSetAttribute(gemm_kernel, cudaFuncAttributePreferredSharedMemoryCarveout, 100);
    dummy_kernel<<<1, 32>>>();                       // 3 dummies -> prep is 4th
    dummy_kernel<<<1, 32>>>();                       // launch = ncu's profiled slot
    dummy_kernel<<<1, 32>>>();
    prep_kernel<<<CK2, 64>>>(mix, loc, tril);
    gbuild_kernel<<<dim3(PPAD / 64, NB / 64), 256>>>(rep);
    gemm_kernel<<<dim3(NB / BM, CK2 / BN), 128, SMEM_B>>>();
    softmax_kernel<<<NB / 8, 256>>>((float*)d_out);
}